// round 2
// baseline (speedup 1.0000x reference)
#include <cuda_runtime.h>

// Problem constants
constexpr int Bc   = 2;
constexpr int Sc   = 2048;
constexpr int HIDc = 1024;
constexpr int NHc  = 16;
constexpr int HDc  = 64;           // HID / NH
constexpr int Mtot = Bc * Sc;      // 4096
constexpr size_t CHUNK = (size_t)Bc * Sc * HIDc;  // 4,194,304 floats
constexpr int NROWS = Bc * NHc * Sc;              // 65536 softmax rows

// Scratch: [0]=Q, [1]=K, [2]=V, [3]=ctx (attn @ V, in [B,S,HID] layout)
__device__ float g_buf[4 * CHUNK];
__device__ float g_rowsum[NROWS];

// ---------------------------------------------------------------------------
// Zero the rowsum accumulator (must happen every replay; atomics accumulate).
// ---------------------------------------------------------------------------
__global__ void zero_rowsum_kernel()
{
    const int i = blockIdx.x * blockDim.x + threadIdx.x;
    ((float4*)g_rowsum)[i] = make_float4(0.f, 0.f, 0.f, 0.f);
}

// ---------------------------------------------------------------------------
// SGEMM NT + bias: C[m,n] = sum_k A[m,k] * W[n,k] + bias[n]
// BM=128, BN=128, BK=8, 256 threads, 8x8 per thread.
// ---------------------------------------------------------------------------
__global__ __launch_bounds__(256) void sgemm_nt_bias(
    const float* __restrict__ Aext, int a_sel,
    const float* __restrict__ W, const float* __restrict__ bias,
    float* __restrict__ Cext, int c_sel,
    int M, int N, int K)
{
    const float* A = (a_sel >= 0) ? (const float*)(g_buf + (size_t)a_sel * CHUNK) : Aext;
    float*       C = (c_sel >= 0) ? (g_buf + (size_t)c_sel * CHUNK) : Cext;

    constexpr int BM = 128, BN = 128, BK = 8, TM = 8, TN = 8;
    __shared__ float As[BK][BM + 4];
    __shared__ float Ws[BK][BN + 4];

    const int tid = threadIdx.x;
    const int tx = tid & 15, ty = tid >> 4;
    const int bm = blockIdx.y * BM, bn = blockIdx.x * BN;

    const int lrow = tid >> 1;        // 0..127
    const int lcol = (tid & 1) * 4;   // 0 or 4
    const float* Ap = A + (size_t)(bm + lrow) * K + lcol;
    const float* Wp = W + (size_t)(bn + lrow) * K + lcol;

    float acc[TM][TN];
    #pragma unroll
    for (int i = 0; i < TM; i++)
        #pragma unroll
        for (int j = 0; j < TN; j++) acc[i][j] = 0.0f;

    for (int k0 = 0; k0 < K; k0 += BK) {
        float4 av = *(const float4*)(Ap + k0);
        float4 wv = *(const float4*)(Wp + k0);
        As[lcol + 0][lrow] = av.x; As[lcol + 1][lrow] = av.y;
        As[lcol + 2][lrow] = av.z; As[lcol + 3][lrow] = av.w;
        Ws[lcol + 0][lrow] = wv.x; Ws[lcol + 1][lrow] = wv.y;
        Ws[lcol + 2][lrow] = wv.z; Ws[lcol + 3][lrow] = wv.w;
        __syncthreads();
        #pragma unroll
        for (int kk = 0; kk < BK; kk++) {
            float a[TM], b[TN];
            *(float4*)&a[0] = *(const float4*)&As[kk][ty * TM];
            *(float4*)&a[4] = *(const float4*)&As[kk][ty * TM + 4];
            *(float4*)&b[0] = *(const float4*)&Ws[kk][tx * TN];
            *(float4*)&b[4] = *(const float4*)&Ws[kk][tx * TN + 4];
            #pragma unroll
            for (int i = 0; i < TM; i++)
                #pragma unroll
                for (int j = 0; j < TN; j++)
                    acc[i][j] = fmaf(a[i], b[j], acc[i][j]);
        }
        __syncthreads();
    }

    #pragma unroll
    for (int i = 0; i < TM; i++) {
        const int m = bm + ty * TM + i;
        #pragma unroll
        for (int j = 0; j < TN; j += 4) {
            const int n = bn + tx * TN + j;
            float4 o;
            o.x = acc[i][j + 0] + bias[n + 0];
            o.y = acc[i][j + 1] + bias[n + 1];
            o.z = acc[i][j + 2] + bias[n + 2];
            o.w = acc[i][j + 3] + bias[n + 3];
            *(float4*)(C + (size_t)m * N + n) = o;
        }
    }
}

// ---------------------------------------------------------------------------
// Scores+exp: attn[b,h,q,k] = exp( (Q.K)/8 + beta*sim ), masked -> 0.
// 128x128 tile per block, 8x8 per thread. Accumulates per-row partial sums
// of exp into g_rowsum via atomics (softmax shift c=0 is exact; scores are
// O(10) so fp32 exp cannot overflow).
// ---------------------------------------------------------------------------
__global__ __launch_bounds__(256) void scores_exp_kernel(
    const float* __restrict__ sim, const int* __restrict__ amask,
    const float* __restrict__ beta_p, float* __restrict__ attn)
{
    const float* Q  = g_buf;
    const float* Kh = g_buf + CHUNK;

    constexpr int BQ = 128, BKt = 128, BD = 8;
    __shared__ float Qs[BD][BQ + 4];
    __shared__ float Ks[BD][BKt + 4];
    __shared__ float red[BQ][17];

    const int bh = blockIdx.z, b = bh >> 4, h = bh & 15;
    const int q0 = blockIdx.y * BQ, k0 = blockIdx.x * BKt;
    const int tid = threadIdx.x, tx = tid & 15, ty = tid >> 4;

    const int lrow = tid >> 1;        // 0..127
    const int lcol = (tid & 1) * 4;   // 0 or 4
    const float* Qp = Q  + ((size_t)b * Sc + q0 + lrow) * HIDc + h * HDc + lcol;
    const float* Kp = Kh + ((size_t)b * Sc + k0 + lrow) * HIDc + h * HDc + lcol;

    float acc[8][8];
    #pragma unroll
    for (int i = 0; i < 8; i++)
        #pragma unroll
        for (int j = 0; j < 8; j++) acc[i][j] = 0.0f;

    #pragma unroll
    for (int d0 = 0; d0 < HDc; d0 += BD) {
        float4 qv = *(const float4*)(Qp + d0);
        float4 kv = *(const float4*)(Kp + d0);
        Qs[lcol + 0][lrow] = qv.x; Qs[lcol + 1][lrow] = qv.y;
        Qs[lcol + 2][lrow] = qv.z; Qs[lcol + 3][lrow] = qv.w;
        Ks[lcol + 0][lrow] = kv.x; Ks[lcol + 1][lrow] = kv.y;
        Ks[lcol + 2][lrow] = kv.z; Ks[lcol + 3][lrow] = kv.w;
        __syncthreads();
        #pragma unroll
        for (int kk = 0; kk < BD; kk++) {
            float a[8], c[8];
            *(float4*)&a[0] = *(const float4*)&Qs[kk][ty * 8];
            *(float4*)&a[4] = *(const float4*)&Qs[kk][ty * 8 + 4];
            *(float4*)&c[0] = *(const float4*)&Ks[kk][tx * 8];
            *(float4*)&c[4] = *(const float4*)&Ks[kk][tx * 8 + 4];
            #pragma unroll
            for (int i = 0; i < 8; i++)
                #pragma unroll
                for (int j = 0; j < 8; j++)
                    acc[i][j] = fmaf(a[i], c[j], acc[i][j]);
        }
        __syncthreads();
    }

    const float beta = *beta_p;
    const float scale = 0.125f;  // 1/sqrt(64)
    const int kcol = k0 + tx * 8;
    const int4 m0 = *(const int4*)(amask + (size_t)b * Sc + kcol);
    const int4 m1 = *(const int4*)(amask + (size_t)b * Sc + kcol + 4);

    float rsum[8];
    #pragma unroll
    for (int i = 0; i < 8; i++) {
        const int q = q0 + ty * 8 + i;
        const float* simp = sim + ((size_t)b * Sc + q) * Sc + kcol;
        const float4 s0 = *(const float4*)simp;
        const float4 s1 = *(const float4*)(simp + 4);
        float e[8];
        e[0] = (m0.x == 0) ? 0.0f : __expf(fmaf(beta, s0.x, acc[i][0] * scale));
        e[1] = (m0.y == 0) ? 0.0f : __expf(fmaf(beta, s0.y, acc[i][1] * scale));
        e[2] = (m0.z == 0) ? 0.0f : __expf(fmaf(beta, s0.z, acc[i][2] * scale));
        e[3] = (m0.w == 0) ? 0.0f : __expf(fmaf(beta, s0.w, acc[i][3] * scale));
        e[4] = (m1.x == 0) ? 0.0f : __expf(fmaf(beta, s1.x, acc[i][4] * scale));
        e[5] = (m1.y == 0) ? 0.0f : __expf(fmaf(beta, s1.y, acc[i][5] * scale));
        e[6] = (m1.z == 0) ? 0.0f : __expf(fmaf(beta, s1.z, acc[i][6] * scale));
        e[7] = (m1.w == 0) ? 0.0f : __expf(fmaf(beta, s1.w, acc[i][7] * scale));
        float* op = attn + ((size_t)bh * Sc + q) * Sc + kcol;
        *(float4*)op       = make_float4(e[0], e[1], e[2], e[3]);
        *(float4*)(op + 4) = make_float4(e[4], e[5], e[6], e[7]);
        rsum[i] = ((e[0] + e[1]) + (e[2] + e[3])) + ((e[4] + e[5]) + (e[6] + e[7]));
    }

    // Block-level row reduction, then one atomic per row.
    #pragma unroll
    for (int i = 0; i < 8; i++) red[ty * 8 + i][tx] = rsum[i];
    __syncthreads();
    if (tid < BQ) {
        float s = 0.0f;
        #pragma unroll
        for (int j = 0; j < 16; j++) s += red[tid][j];
        atomicAdd(&g_rowsum[(size_t)bh * Sc + q0 + tid], s);
    }
}

// ---------------------------------------------------------------------------
// Fused normalize + AV:
//   reads exp-scores from attn, w = e * (1/rowsum), writes w back (final
//   attention_weights output) and accumulates ctx = w @ V.
// 128 (q) x 64 (d) tile per block, k-chunks of 32, 8x4 per thread.
// ---------------------------------------------------------------------------
__global__ __launch_bounds__(256) void av_norm_kernel(float* __restrict__ attn)
{
    const float* V = g_buf + 2 * CHUNK;
    float*     ctx = g_buf + 3 * CHUNK;

    constexpr int BQ = 128, BKk = 32;
    __shared__ float As[BKk][BQ + 4];
    __shared__ float Vs[BKk][HDc + 4];
    __shared__ float inv[BQ];

    const int bh = blockIdx.z, b = bh >> 4, h = bh & 15;
    const int q0 = blockIdx.x * BQ;
    const int tid = threadIdx.x, tx = tid & 15, ty = tid >> 4;

    if (tid < BQ) inv[tid] = 1.0f / g_rowsum[(size_t)bh * Sc + q0 + tid];
    __syncthreads();

    float* Abase = attn + ((size_t)bh * Sc + q0) * Sc;
    const float* Vbase = V + (size_t)b * Sc * HIDc + h * HDc;

    float acc[8][4];
    #pragma unroll
    for (int i = 0; i < 8; i++)
        #pragma unroll
        for (int j = 0; j < 4; j++) acc[i][j] = 0.0f;

    for (int k0 = 0; k0 < Sc; k0 += BKk) {
        // exp tile: 128 rows x 32 cols, normalize, stash to smem + write back.
        #pragma unroll
        for (int L = 0; L < 4; L++) {
            const int e  = tid + L * 256;
            const int ar = e >> 3, ac = (e & 7) * 4;
            float* gp = Abase + (size_t)ar * Sc + k0 + ac;
            float4 av = *(const float4*)gp;
            const float iv = inv[ar];
            av.x *= iv; av.y *= iv; av.z *= iv; av.w *= iv;
            As[ac + 0][ar] = av.x; As[ac + 1][ar] = av.y;
            As[ac + 2][ar] = av.z; As[ac + 3][ar] = av.w;
            *(float4*)gp = av;   // final attention weights
        }
        // V tile: 32 rows x 64 cols.
        #pragma unroll
        for (int L = 0; L < 2; L++) {
            const int e  = tid + L * 256;
            const int vr = e >> 4, vc = (e & 15) * 4;
            *(float4*)&Vs[vr][vc] =
                *(const float4*)(Vbase + (size_t)(k0 + vr) * HIDc + vc);
        }
        __syncthreads();
        #pragma unroll
        for (int kk = 0; kk < BKk; kk++) {
            float a[8], v[4];
            *(float4*)&a[0] = *(const float4*)&As[kk][ty * 8];
            *(float4*)&a[4] = *(const float4*)&As[kk][ty * 8 + 4];
            *(float4*)&v[0] = *(const float4*)&Vs[kk][tx * 4];
            #pragma unroll
            for (int i = 0; i < 8; i++)
                #pragma unroll
                for (int j = 0; j < 4; j++)
                    acc[i][j] = fmaf(a[i], v[j], acc[i][j]);
        }
        __syncthreads();
    }

    #pragma unroll
    for (int i = 0; i < 8; i++) {
        const int q = q0 + ty * 8 + i;
        float4 o = make_float4(acc[i][0], acc[i][1], acc[i][2], acc[i][3]);
        *(float4*)(ctx + ((size_t)b * Sc + q) * HIDc + h * HDc + tx * 4) = o;
    }
}

// ---------------------------------------------------------------------------
// Launcher
// ---------------------------------------------------------------------------
extern "C" void kernel_launch(void* const* d_in, const int* in_sizes, int n_in,
                              void* d_out, int out_size)
{
    const float* query = (const float*)d_in[0];
    const float* key   = (const float*)d_in[1];
    const float* value = (const float*)d_in[2];
    const int*   amask = (const int*)  d_in[3];
    const float* sim   = (const float*)d_in[4];
    const float* Wq    = (const float*)d_in[5];
    const float* bq    = (const float*)d_in[6];
    const float* Wk    = (const float*)d_in[7];
    const float* bk    = (const float*)d_in[8];
    const float* Wv    = (const float*)d_in[9];
    const float* bv    = (const float*)d_in[10];
    const float* Wo    = (const float*)d_in[11];
    const float* bo    = (const float*)d_in[12];
    const float* beta  = (const float*)d_in[13];

    float* out  = (float*)d_out;
    float* attn = out + CHUNK;   // attention_weights region [B,NH,S,S]

    zero_rowsum_kernel<<<NROWS / (256 * 4), 256>>>();

    dim3 gp(HIDc / 128, Mtot / 128);                  // (8, 32)
    sgemm_nt_bias<<<gp, 256>>>(query, -1, Wq, bq, nullptr, 0, Mtot, HIDc, HIDc);
    sgemm_nt_bias<<<gp, 256>>>(key,   -1, Wk, bk, nullptr, 1, Mtot, HIDc, HIDc);
    sgemm_nt_bias<<<gp, 256>>>(value, -1, Wv, bv, nullptr, 2, Mtot, HIDc, HIDc);

    dim3 gs(Sc / 128, Sc / 128, Bc * NHc);            // (16, 16, 32)
    scores_exp_kernel<<<gs, 256>>>(sim, amask, beta, attn);

    dim3 ga(Sc / 128, 1, Bc * NHc);                   // (16, 1, 32)
    av_norm_kernel<<<ga, 256>>>(attn);

    sgemm_nt_bias<<<gp, 256>>>(nullptr, 3, Wo, bo, out, -1, Mtot, HIDc, HIDc);
}